// round 8
// baseline (speedup 1.0000x reference)
#include <cuda_runtime.h>
#include <cstdint>

// BlockMaskGenerator: 4 random rectangles per batch -> 256 x 16384 bool
// target mask + complement context mask (bool promoted to f32 by harness).
//   d_out = [context_mask (256*16384 f32), target_mask (256*16384 f32)]
// R7 postmortem: per-warp rect chain (MUFU/casts/shfl ~1000+cyc dependent
// latency in every warp) bounds issue, not stores. R8: two-kernel split —
// kernel A computes 1024 packed rects once into __device__ scratch; kernel B
// (R6's proven coalesced geometry) does one broadcast LDG.128 + pure stores.

#define BM_BATCH   256
#define BM_NBLK    4
#define BM_H       128
#define BM_W       128
#define BM_SEQ     (BM_H * BM_W)
#define BM_TOTAL   (BM_BATCH * BM_NBLK)

__device__ __align__(16) unsigned g_rects[BM_TOTAL];   // top|bot<<8|left<<16|right<<24

__global__ __launch_bounds__(256)
void rect_kernel(const float* __restrict__ scales_u,
                 const float* __restrict__ rand_top,
                 const float* __restrict__ rand_left)
{
    const int i = blockIdx.x * 256 + threadIdx.x;
    if (i >= BM_TOTAL) return;
    // scales = 0.15 + u*0.05 (separate mul/add, f32 rn — match JAX; no FMA)
    float scale = __fadd_rn(0.15f, __fmul_rn(scales_u[i], 0.05f));
    float areaf = __fmul_rn(__fmul_rn(scale, 128.0f), 128.0f);   // pow2 exact
    int area = (int)areaf;                                       // trunc
    int h = (int)__fsqrt_rn(__fdiv_rn((float)area, 0.75f));
    h = min(max(h, 1), BM_H);
    int w = (int)__fdiv_rn((float)area, (float)h);
    w = min(max(w, 1), BM_W);
    int max_t = max(BM_H - h + 1, 1);
    int max_l = max(BM_W - w + 1, 1);
    int top  = (int)__fmul_rn(rand_top[i],  (float)max_t);
    int left = (int)__fmul_rn(rand_left[i], (float)max_l);
    g_rects[i] = (unsigned)top | ((unsigned)(top + h) << 8)
               | ((unsigned)left << 16) | ((unsigned)(left + w) << 24);
}

__global__ __launch_bounds__(256, 8)
void block_mask_kernel(float* __restrict__ out)
{
    const int bid  = blockIdx.x;
    const int b    = bid >> 2;                  // batch (4 CTAs per batch)
    const int tid  = threadIdx.x;
    const int lane = tid & 31;
    const int warp = tid >> 5;

    // One broadcast LDG.128: all 4 packed rects for this batch.
    const uint4 pr = *reinterpret_cast<const uint4*>(&g_rects[b * BM_NBLK]);
    const unsigned pk[4] = {pr.x, pr.y, pr.z, pr.w};

    // Warp owns 4 consecutive rows; lane owns cols [4*lane, 4*lane+4).
    const int row0 = (bid & 3) * 32 + warp * 4;
    const int c0   = lane * 4;

    unsigned m[4] = {0u, 0u, 0u, 0u};
#pragma unroll
    for (int j = 0; j < BM_NBLK; j++) {
        const unsigned p = pk[j];
        int tj = (int)(p & 0xFFu);
        int bj = (int)((p >> 8) & 0xFFu);
        int lj = (int)((p >> 16) & 0xFFu);
        int rj = (int)(p >> 24);

        int clo = max(lj - c0, 0);
        int chi = min(rj - c0, 4);
        unsigned cm = (chi > clo) ? (((1u << chi) - 1u) & ~((1u << clo) - 1u)) : 0u;

        int rlo = min(max(tj - row0, 0), 4);
        int rhi = min(max(bj - row0, 0), 4);
        unsigned rm = ((1u << rhi) - 1u) & ~((1u << rlo) - 1u);

#pragma unroll
        for (int r = 0; r < 4; r++)
            m[r] |= cm & (0u - ((rm >> r) & 1u));
    }

    const unsigned ONE = 0x3F800000u;  // 1.0f
    float* ctx = out;
    float* tgt = out + (size_t)BM_BATCH * BM_SEQ;
    // lane l writes 16B at row*512 + l*16 -> each warp STG.128 = contiguous 512B
    const size_t base = (size_t)b * BM_SEQ + (size_t)row0 * BM_W + c0;

#pragma unroll
    for (int r = 0; r < 4; r++) {
        uint4 t;
        t.x = (m[r] & 1u) ? ONE : 0u;
        t.y = (m[r] & 2u) ? ONE : 0u;
        t.z = (m[r] & 4u) ? ONE : 0u;
        t.w = (m[r] & 8u) ? ONE : 0u;
        *reinterpret_cast<uint4*>(tgt + base + (size_t)r * BM_W) = t;
    }
#pragma unroll
    for (int r = 0; r < 4; r++) {
        uint4 c;
        c.x = (m[r] & 1u) ? 0u : ONE;
        c.y = (m[r] & 2u) ? 0u : ONE;
        c.z = (m[r] & 4u) ? 0u : ONE;
        c.w = (m[r] & 8u) ? 0u : ONE;
        *reinterpret_cast<uint4*>(ctx + base + (size_t)r * BM_W) = c;
    }
}

extern "C" void kernel_launch(void* const* d_in, const int* in_sizes, int n_in,
                              void* d_out, int out_size)
{
    const float* scales_u  = (const float*)d_in[0];
    const float* rand_top  = (const float*)d_in[1];
    const float* rand_left = (const float*)d_in[2];
    float* out = (float*)d_out;

    rect_kernel<<<(BM_TOTAL + 255) / 256, 256>>>(scales_u, rand_top, rand_left);
    block_mask_kernel<<<BM_BATCH * 4, 256>>>(out);
}